// round 13
// baseline (speedup 1.0000x reference)
#include <cuda_runtime.h>
#include <math.h>
#include <stdint.h>

#define BN_EPS 1e-5f
#define WPB 12                 /* warps per block */
#define NT 384
#define DEPTH 2                /* per-warp ring depth (pairs) */
#define BPSM 2
#define NSM 148
#define GRID (NSM * BPSM)      /* 296 blocks, guaranteed co-resident */
#define TWP (GRID * WPB)       /* 3552 pair stride */
#define MAXB 65536
#define PAIR_FLOATS 1152
#define PAIR_BYTES  4608

// persistent scratch (no allocation allowed)
__device__ float g_zbuf[MAXB * 4];
__device__ float g_part[GRID * 8];
__device__ unsigned g_bar;     // monotone arrival counter (never reset)

__device__ __forceinline__ uint32_t smem_u32(const void* p) {
    uint32_t a;
    asm("{ .reg .u64 t; cvta.to.shared.u64 t, %1; cvt.u32.u64 %0, t; }"
        : "=r"(a) : "l"(p));
    return a;
}
__device__ __forceinline__ void mbar_init(uint32_t m, uint32_t cnt) {
    asm volatile("mbarrier.init.shared.b64 [%0], %1;" :: "r"(m), "r"(cnt) : "memory");
}
__device__ __forceinline__ void mbar_expect_tx(uint32_t m, uint32_t bytes) {
    asm volatile("mbarrier.arrive.expect_tx.shared.b64 _, [%0], %1;"
                 :: "r"(m), "r"(bytes) : "memory");
}
__device__ __forceinline__ void bulk_ld(uint32_t dst, const void* src,
                                        uint32_t bytes, uint32_t m) {
    asm volatile("cp.async.bulk.shared::cluster.global.mbarrier::complete_tx::bytes "
                 "[%0], [%1], %2, [%3];"
                 :: "r"(dst), "l"(src), "r"(bytes), "r"(m) : "memory");
}
__device__ __forceinline__ void mbar_wait(uint32_t m, uint32_t phase) {
    uint32_t done;
    asm volatile("{\n\t.reg .pred p;\n\t"
                 "mbarrier.try_wait.parity.acquire.cta.shared::cta.b64 p, [%1], %2;\n\t"
                 "selp.b32 %0, 1, 0, p;\n\t}"
                 : "=r"(done) : "r"(m), "r"(phase) : "memory");
    if (!done) {
        asm volatile("{\n\t.reg .pred P1;\n\t"
                     "W_%=:\n\t"
                     "mbarrier.try_wait.parity.acquire.cta.shared::cta.b64 P1, [%0], %1, 0x989680;\n\t"
                     "@P1 bra.uni D_%=;\n\t"
                     "bra.uni W_%=;\n\t"
                     "D_%=:\n\t}" :: "r"(m), "r"(phase) : "memory");
    }
}

__global__ void __launch_bounds__(NT, BPSM) k_fused(
        const float* __restrict__ x,
        const float* __restrict__ enc_w,
        const float* __restrict__ enc_b,
        const float* __restrict__ vp,
        const float* __restrict__ gamma,
        const float* __restrict__ beta,
        float* __restrict__ out,
        int B)
{
    // per-warp private 2-deep pair rings: 12*2*1152 floats = 110592 B
    __shared__ __align__(128) float buf[WPB * DEPTH * PAIR_FLOATS];
    __shared__ __align__(8) uint64_t mbar[WPB * DEPTH];
    // overlay: Us (init-only, 512 floats) shares with pw(576)+wacc(96)
    __shared__ __align__(16) float ovl[WPB * 48 + WPB * 8];
    __shared__ float encs[68];        // enc_w(64) + enc_b(4)
    __shared__ float stat[8];

    float* const Us = ovl;                         // [2*256] init only
    float (*const pw)[48] = (float(*)[48])ovl;     // [WPB][48] loop time
    float* const wacc = ovl + WPB * 48;            // [WPB*8] epilogue

    const int tid = threadIdx.x;
    const int wid = tid >> 5;
    const int lid = tid & 31;
    const long gwp = (long)blockIdx.x * WPB + wid;   // global pair id

    const uint32_t mybuf0 = smem_u32(&buf[wid * DEPTH * PAIR_FLOATS]);
    const uint32_t mymb0  = smem_u32(&mbar[wid * DEPTH]);

    // ---- stage encoder ----
    if (tid >= 32 && tid < 96)  encs[tid - 32] = enc_w[tid - 32];
    if (tid >= 96 && tid < 100) encs[64 + tid - 96] = enc_b[tid - 96];

    // ---- per-warp prologue: own mbarriers + DEPTH pair prefetches ----
    if (lid == 0) {
#pragma unroll
        for (int d = 0; d < DEPTH; d++) mbar_init(mymb0 + d * 8, 1);
        asm volatile("fence.proxy.async.shared::cta;" ::: "memory");
#pragma unroll
        for (int d = 0; d < DEPTH; d++) {
            long s0 = 2 * (gwp + (long)d * TWP);
            if (s0 < B) {
                uint32_t bytes = (uint32_t)min(2L, B - s0) * 2304u;
                mbar_expect_tx(mymb0 + d * 8, bytes);
                bulk_ld(mybuf0 + d * PAIR_BYTES, x + s0 * 576, bytes, mymb0 + d * 8);
            }
        }
    }

    // ---- warp 0: build fixed variational unitary U (fast sincos) ----
    if (tid < 16) {
        float re[16], im[16];
#pragma unroll
        for (int b = 0; b < 16; b++) { re[b] = (b == tid) ? 1.f : 0.f; im[b] = 0.f; }
#pragma unroll
        for (int d = 0; d < 2; d++) {
#pragma unroll
            for (int w = 0; w < 4; w++) {
                const int mask = 8 >> w;
                float cx, sx, cy, sy, cz, sz;
                __sincosf(0.5f * vp[d * 12 + w * 3 + 0], &sx, &cx);
                __sincosf(0.5f * vp[d * 12 + w * 3 + 1], &sy, &cy);
                __sincosf(0.5f * vp[d * 12 + w * 3 + 2], &sz, &cz);
#pragma unroll
                for (int b = 0; b < 16; b++) {
                    if (b & mask) continue;
                    const int b1 = b | mask;
                    float r0, i0, r1, i1;
                    r0 = re[b]; i0 = im[b]; r1 = re[b1]; i1 = im[b1];
                    re[b]  = cx * r0 + sx * i1;  im[b]  = cx * i0 - sx * r1;
                    re[b1] = cx * r1 + sx * i0;  im[b1] = cx * i1 - sx * r0;
                    r0 = re[b]; i0 = im[b]; r1 = re[b1]; i1 = im[b1];
                    re[b]  = cy * r0 - sy * r1;  im[b]  = cy * i0 - sy * i1;
                    re[b1] = sy * r0 + cy * r1;  im[b1] = sy * i0 + cy * i1;
                    r0 = re[b]; i0 = im[b]; r1 = re[b1]; i1 = im[b1];
                    re[b]  = cz * r0 + sz * i0;  im[b]  = cz * i0 - sz * r0;
                    re[b1] = cz * r1 - sz * i1;  im[b1] = cz * i1 + sz * r1;
                }
            }
#pragma unroll
            for (int c = 0; c < 4; c++) {
                const int tg = (c + 1) & 3;
                const int mc = 8 >> c, mt = 8 >> tg;
#pragma unroll
                for (int b = 0; b < 16; b++) {
                    if ((b & mc) && !(b & mt)) {
                        const int b1 = b | mt;
                        float tr = re[b], ti = im[b];
                        re[b] = re[b1]; im[b] = im[b1];
                        re[b1] = tr;    im[b1] = ti;
                    }
                }
            }
        }
#pragma unroll
        for (int b = 0; b < 16; b++) {
            Us[b * 16 + tid]       = re[b];
            Us[256 + b * 16 + tid] = im[b];
        }
    }
    __syncthreads();

    // ---- my U row into registers, sign-folded by (-i)^popc(col) ----
    const int cj = lid & 15;
    float fr[16], fi[16];
#pragma unroll
    for (int t = 0; t < 16; t++) {
        float urv = Us[cj * 16 + t], uiv = Us[256 + cj * 16 + t];
        const int k4 = __popc(t) & 3;
        if (k4 == 0)      { fr[t] = urv;  fi[t] = uiv;  }
        else if (k4 == 1) { fr[t] = uiv;  fi[t] = -urv; }
        else if (k4 == 2) { fr[t] = -urv; fi[t] = -uiv; }
        else              { fr[t] = -uiv; fi[t] = urv;  }
    }
    __syncthreads();   // ALL warps done reading Us before pw overwrites it

    // ---- conflict-free pooling lane decomposition ----
    const int pwy = lid >> 3;
    const int phh = (lid >> 2) & 1;
    const int pwx = lid & 3;
    const int f0  = 72 * pwy + 36 * phh + 3 * pwx;   // float2 units
    const int half = lid >> 4;                        // circuit: 0=A, 1=B

    // WHT output lanes: cj in {8,4,2,1} hold z-components
    const bool is_z = (cj == 1) || (cj == 2) || (cj == 4) || (cj == 8);
    const int zidx = is_z ? (__clz(cj) - 28) : 0;     // 8->0, 4->1, 2->2, 1->3

    float accS = 0.f, accQ = 0.f;

    // ============ per-warp pair loop (no block syncs) ============
    int it = 0;
    for (long pr = gwp; 2 * pr < B; pr += TWP, it++) {
        const int stage = it % DEPTH;
        const uint32_t mb = mymb0 + stage * 8;
        const long samp0 = 2 * pr;

        mbar_wait(mb, (it / DEPTH) & 1);

        // ---- pooling: conflict-free LDS.64 (int-indexed float2) ----
        {
            const float2* p = (const float2*)(&buf[(wid * DEPTH + stage) * PAIR_FLOATS]) + f0;
#pragma unroll
            for (int smp = 0; smp < 2; smp++) {
                const float2* q = p + smp * 288;
                float s = 0.f;
#pragma unroll
                for (int dy = 0; dy < 3; dy++) {
                    float2 a = q[dy * 12 + 0];
                    float2 b = q[dy * 12 + 1];
                    float2 c = q[dy * 12 + 2];
                    s += a.x + a.y + b.x + b.y + c.x + c.y;
                }
                s += __shfl_down_sync(0xffffffffu, s, 4);
                if (phh == 0)
                    pw[wid][smp * 16 + pwy * 4 + pwx] = s * (1.f / 36.f);
            }
        }
        __syncwarp();   // sync1: pooled visible to angle lanes

        // ---- refill this slot for pair + DEPTH*TWP (overlaps compute) ----
        if (lid == 0) {
            long sn = 2 * (pr + (long)DEPTH * TWP);
            if (sn < B) {
                uint32_t bytes = (uint32_t)min(2L, B - sn) * 2304u;
                mbar_expect_tx(mb, bytes);
                bulk_ld(mybuf0 + stage * PAIR_BYTES, x + sn * 576, bytes, mb);
            }
        }

        // ---- angles + sincos: lanes 0..7 (4 per sample) ----
        if (lid < 8) {
            const int smp = lid >> 2, i = lid & 3;
            const float* pp = &pw[wid][smp * 16];
            float a0 = encs[64 + i], a1 = 0.f;
#pragma unroll
            for (int kk = 0; kk < 8; kk++) {
                a0 = fmaf(encs[i * 16 + kk], pp[kk], a0);
                a1 = fmaf(encs[i * 16 + 8 + kk], pp[8 + kk], a1);
            }
            float sv, cv;
            __sincosf(0.5f * (a0 + a1), &sv, &cv);
            pw[wid][32 + smp * 8 + i] = cv;
            pw[wid][32 + smp * 8 + 4 + i] = sv;
        }
        __syncwarp();   // sync2: cos/sin visible to circuit lanes

        // ---- circuit: lanes 0-15 sample A, lanes 16-31 sample B ----
        float v;
        {
            const float* c = &pw[wid][32 + half * 8];
            float c0 = c[0], c1 = c[1], c2 = c[2], c3 = c[3];
            float s0 = c[4], s1 = c[5], s2 = c[6], s3 = c[7];
            float p01[4], p23[4];
            p01[0] = c0 * c1; p01[1] = c0 * s1; p01[2] = s0 * c1; p01[3] = s0 * s1;
            p23[0] = c2 * c3; p23[1] = c2 * s3; p23[2] = s2 * c3; p23[3] = s2 * s3;
            float ar = 0.f, ai = 0.f;
#pragma unroll
            for (int t = 0; t < 16; t++) {
                float av = p01[t >> 2] * p23[t & 3];
                ar = fmaf(fr[t], av, ar);
                ai = fmaf(fi[t], av, ai);
            }
            v = ar * ar + ai * ai;   // p_cj
        }
        // ---- 16-point WHT butterfly: lane m -> sum_j (-1)^popc(j&m) p_j ----
#pragma unroll
        for (int b = 0; b < 4; b++) {
            float o = __shfl_xor_sync(0xffffffffu, v, 1 << b);
            v = (cj & (1 << b)) ? (o - v) : (v + o);
        }
        // lanes with cj in {8,4,2,1} now hold z components
        if (is_z && samp0 + half < B) {
            g_zbuf[(samp0 + half) * 4 + zidx] = v;
            accS += v;
            accQ += v * v;
        }
    }

    // ---- merge B-half accumulators into A-half z-lanes (deterministic) ----
    accS += __shfl_down_sync(0xffffffffu, accS, 16);
    accQ += __shfl_down_sync(0xffffffffu, accQ, 16);
    __syncthreads();   // all warps done with pw before wacc overlay use
    if (is_z && half == 0) {
        wacc[wid * 8 + zidx]     = accS;
        wacc[wid * 8 + 4 + zidx] = accQ;
    }
    __syncthreads();
    if (tid < 4) {
        float S = 0.f, Q = 0.f;
#pragma unroll
        for (int w = 0; w < WPB; w++) {
            S += wacc[w * 8 + tid];
            Q += wacc[w * 8 + 4 + tid];
        }
        g_part[blockIdx.x * 8 + tid]     = S;
        g_part[blockIdx.x * 8 + 4 + tid] = Q;
    }
    __threadfence();
    __syncthreads();
    if (tid == 0) {
        unsigned arr = atomicAdd(&g_bar, 1u) + 1u;
        unsigned target = ((arr + GRID - 1u) / GRID) * GRID;  // this launch's release
        while (*((volatile unsigned*)&g_bar) < target) {}
        __threadfence();
    }
    __syncthreads();

    // ---- redundant-but-deterministic stats reduction (each block) ----
    {
        float* red = &buf[0];   // reuse smem
        const int w = tid & 7, rr = tid >> 3;
        if (tid < 256) {
            float S = 0.f;
            for (int i = rr; i < GRID; i += 32) S += g_part[i * 8 + w];
            red[tid] = S;
        }
        __syncthreads();
#pragma unroll
        for (int step = 128; step >= 8; step >>= 1) {
            if (tid < step) red[tid] += red[tid + step];
            __syncthreads();
        }
        if (tid < 4) {
            float mean = red[tid] / (float)B;
            float var  = red[4 + tid] / (float)B - mean * mean;
            float sc   = gamma[tid] * rsqrtf(var + BN_EPS);
            stat[tid]     = sc;
            stat[4 + tid] = beta[tid] - mean * sc;
        }
        __syncthreads();
    }

    // ---- normalize (z is L2-resident) ----
    const float n0 = stat[0], n1 = stat[1], n2 = stat[2], n3 = stat[3];
    const float h0 = stat[4], h1 = stat[5], h2 = stat[6], h3 = stat[7];
    for (int b = blockIdx.x * NT + tid; b < B; b += GRID * NT) {
        float4 z = ((const float4*)g_zbuf)[b];
        ((float4*)out)[b] = make_float4(fmaf(z.x, n0, h0), fmaf(z.y, n1, h1),
                                        fmaf(z.z, n2, h2), fmaf(z.w, n3, h3));
    }
}

extern "C" void kernel_launch(void* const* d_in, const int* in_sizes, int n_in,
                              void* d_out, int out_size)
{
    const float* x      = (const float*)d_in[0];
    const float* enc_w  = (const float*)d_in[1];
    const float* enc_b  = (const float*)d_in[2];
    const float* vp     = (const float*)d_in[3];
    const float* gamma  = (const float*)d_in[4];
    const float* beta   = (const float*)d_in[5];

    const int B = in_sizes[0] / 576;   // [B,1,24,24]

    k_fused<<<GRID, NT>>>(x, enc_w, enc_b, vp, gamma, beta, (float*)d_out, B);
}

// round 14
// speedup vs baseline: 1.0790x; 1.0790x over previous
#include <cuda_runtime.h>
#include <math.h>
#include <stdint.h>

#define BN_EPS 1e-5f
#define WPB 10                 /* warps per block */
#define NT 320
#define DEPTH 2                /* per-warp ring depth (pairs) */
#define BPSM 2
#define NSM 148
#define GRID (NSM * BPSM)      /* 296 blocks, guaranteed co-resident */
#define TWP (GRID * WPB)       /* 2960 pair stride */
#define MAXB 65536
#define PAIR_FLOATS 1152
#define PAIR_BYTES  4608

typedef unsigned long long ull;

// persistent scratch (no allocation allowed)
__device__ float g_zbuf[MAXB * 4];
__device__ float g_part[GRID * 8];
__device__ unsigned g_bar;     // monotone arrival counter (never reset)

__device__ __forceinline__ uint32_t smem_u32(const void* p) {
    uint32_t a;
    asm("{ .reg .u64 t; cvta.to.shared.u64 t, %1; cvt.u32.u64 %0, t; }"
        : "=r"(a) : "l"(p));
    return a;
}
__device__ __forceinline__ void mbar_init(uint32_t m, uint32_t cnt) {
    asm volatile("mbarrier.init.shared.b64 [%0], %1;" :: "r"(m), "r"(cnt) : "memory");
}
__device__ __forceinline__ void mbar_expect_tx(uint32_t m, uint32_t bytes) {
    asm volatile("mbarrier.arrive.expect_tx.shared.b64 _, [%0], %1;"
                 :: "r"(m), "r"(bytes) : "memory");
}
__device__ __forceinline__ void bulk_ld(uint32_t dst, const void* src,
                                        uint32_t bytes, uint32_t m) {
    asm volatile("cp.async.bulk.shared::cluster.global.mbarrier::complete_tx::bytes "
                 "[%0], [%1], %2, [%3];"
                 :: "r"(dst), "l"(src), "r"(bytes), "r"(m) : "memory");
}
__device__ __forceinline__ void mbar_wait(uint32_t m, uint32_t phase) {
    uint32_t done;
    asm volatile("{\n\t.reg .pred p;\n\t"
                 "mbarrier.try_wait.parity.acquire.cta.shared::cta.b64 p, [%1], %2;\n\t"
                 "selp.b32 %0, 1, 0, p;\n\t}"
                 : "=r"(done) : "r"(m), "r"(phase) : "memory");
    if (!done) {
        asm volatile("{\n\t.reg .pred P1;\n\t"
                     "W_%=:\n\t"
                     "mbarrier.try_wait.parity.acquire.cta.shared::cta.b64 P1, [%0], %1, 0x989680;\n\t"
                     "@P1 bra.uni D_%=;\n\t"
                     "bra.uni W_%=;\n\t"
                     "D_%=:\n\t}" :: "r"(m), "r"(phase) : "memory");
    }
}

#define ADDX2(d, a, b) \
    asm("add.rn.f32x2 %0, %1, %2;" : "=l"(d) : "l"(a), "l"(b))
#define MULX2(d, a, b) \
    asm("mul.rn.f32x2 %0, %1, %2;" : "=l"(d) : "l"(a), "l"(b))
#define FMAX2(d, a, b, c) \
    asm("fma.rn.f32x2 %0, %1, %2, %3;" : "=l"(d) : "l"(a), "l"(b), "l"(c))
#define PACKX2(d, lo, hi) \
    asm("mov.b64 %0, {%1, %2};" : "=l"(d) : "r"(__float_as_uint(lo)), "r"(__float_as_uint(hi)))
__device__ __forceinline__ float x2_hsum(ull v) {
    uint32_t lo, hi;
    asm("mov.b64 {%0, %1}, %2;" : "=r"(lo), "=r"(hi) : "l"(v));
    return __uint_as_float(lo) + __uint_as_float(hi);
}

__global__ void __launch_bounds__(NT, BPSM) k_fused(
        const float* __restrict__ x,
        const float* __restrict__ enc_w,
        const float* __restrict__ enc_b,
        const float* __restrict__ vp,
        const float* __restrict__ gamma,
        const float* __restrict__ beta,
        float* __restrict__ out,
        int B)
{
    // per-warp private 2-deep pair rings: 10*2*1152 floats = 92160 B
    __shared__ __align__(128) float buf[WPB * DEPTH * PAIR_FLOATS];
    __shared__ __align__(8) uint64_t mbar[WPB * DEPTH];
    __shared__ float Us[2 * 256];     // U re|im
    __shared__ float pw[WPB][48];     // pooled A[16] B[16], cs A[8] B[8]
    __shared__ float encs[68];        // enc_w(64) + enc_b(4)
    __shared__ float wacc[WPB][8];    // per-warp BN partials
    __shared__ float stat[8];

    const int tid = threadIdx.x;
    const int wid = tid >> 5;
    const int lid = tid & 31;
    const long gwp = (long)blockIdx.x * WPB + wid;   // global pair id

    const uint32_t mybuf0 = smem_u32(&buf[wid * DEPTH * PAIR_FLOATS]);
    const uint32_t mymb0  = smem_u32(&mbar[wid * DEPTH]);

    // ---- stage encoder ----
    if (tid >= 32 && tid < 96)  encs[tid - 32] = enc_w[tid - 32];
    if (tid >= 96 && tid < 100) encs[64 + tid - 96] = enc_b[tid - 96];

    // ---- per-warp prologue: own mbarriers + DEPTH pair prefetches ----
    if (lid == 0) {
#pragma unroll
        for (int d = 0; d < DEPTH; d++) mbar_init(mymb0 + d * 8, 1);
        asm volatile("fence.proxy.async.shared::cta;" ::: "memory");
#pragma unroll
        for (int d = 0; d < DEPTH; d++) {
            long s0 = 2 * (gwp + (long)d * TWP);
            if (s0 < B) {
                uint32_t bytes = (uint32_t)min(2L, B - s0) * 2304u;
                mbar_expect_tx(mymb0 + d * 8, bytes);
                bulk_ld(mybuf0 + d * PAIR_BYTES, x + s0 * 576, bytes, mymb0 + d * 8);
            }
        }
    }

    // ---- warp 0: build fixed variational unitary U (fast sincos) ----
    if (tid < 16) {
        float re[16], im[16];
#pragma unroll
        for (int b = 0; b < 16; b++) { re[b] = (b == tid) ? 1.f : 0.f; im[b] = 0.f; }
#pragma unroll
        for (int d = 0; d < 2; d++) {
#pragma unroll
            for (int w = 0; w < 4; w++) {
                const int mask = 8 >> w;
                float cx, sx, cy, sy, cz, sz;
                __sincosf(0.5f * vp[d * 12 + w * 3 + 0], &sx, &cx);
                __sincosf(0.5f * vp[d * 12 + w * 3 + 1], &sy, &cy);
                __sincosf(0.5f * vp[d * 12 + w * 3 + 2], &sz, &cz);
#pragma unroll
                for (int b = 0; b < 16; b++) {
                    if (b & mask) continue;
                    const int b1 = b | mask;
                    float r0, i0, r1, i1;
                    r0 = re[b]; i0 = im[b]; r1 = re[b1]; i1 = im[b1];
                    re[b]  = cx * r0 + sx * i1;  im[b]  = cx * i0 - sx * r1;
                    re[b1] = cx * r1 + sx * i0;  im[b1] = cx * i1 - sx * r0;
                    r0 = re[b]; i0 = im[b]; r1 = re[b1]; i1 = im[b1];
                    re[b]  = cy * r0 - sy * r1;  im[b]  = cy * i0 - sy * i1;
                    re[b1] = sy * r0 + cy * r1;  im[b1] = sy * i0 + cy * i1;
                    r0 = re[b]; i0 = im[b]; r1 = re[b1]; i1 = im[b1];
                    re[b]  = cz * r0 + sz * i0;  im[b]  = cz * i0 - sz * r0;
                    re[b1] = cz * r1 - sz * i1;  im[b1] = cz * i1 + sz * r1;
                }
            }
#pragma unroll
            for (int c = 0; c < 4; c++) {
                const int tg = (c + 1) & 3;
                const int mc = 8 >> c, mt = 8 >> tg;
#pragma unroll
                for (int b = 0; b < 16; b++) {
                    if ((b & mc) && !(b & mt)) {
                        const int b1 = b | mt;
                        float tr = re[b], ti = im[b];
                        re[b] = re[b1]; im[b] = im[b1];
                        re[b1] = tr;    im[b1] = ti;
                    }
                }
            }
        }
#pragma unroll
        for (int b = 0; b < 16; b++) {
            Us[b * 16 + tid]       = re[b];
            Us[256 + b * 16 + tid] = im[b];
        }
    }
    __syncthreads();

    // ---- my U row: sign-folded by (-i)^popc(col), packed as f32x2 pairs ----
    const int cj = lid & 15;
    ull frp[8], fip[8];
#pragma unroll
    for (int i = 0; i < 8; i++) {
        float fr2[2], fi2[2];
#pragma unroll
        for (int h = 0; h < 2; h++) {
            const int t = 2 * i + h;
            float urv = Us[cj * 16 + t], uiv = Us[256 + cj * 16 + t];
            const int k4 = __popc(t) & 3;
            if (k4 == 0)      { fr2[h] = urv;  fi2[h] = uiv;  }
            else if (k4 == 1) { fr2[h] = uiv;  fi2[h] = -urv; }
            else if (k4 == 2) { fr2[h] = -urv; fi2[h] = -uiv; }
            else              { fr2[h] = -uiv; fi2[h] = urv;  }
        }
        PACKX2(frp[i], fr2[0], fr2[1]);
        PACKX2(fip[i], fi2[0], fi2[1]);
    }

    // ---- conflict-free pooling lane decomposition ----
    const int pwy = lid >> 3;
    const int phh = (lid >> 2) & 1;
    const int pwx = lid & 3;
    const int f0  = 72 * pwy + 36 * phh + 3 * pwx;   // float2 units
    const int half = lid >> 4;                        // circuit: 0=A, 1=B

    // WHT output lanes: cj in {8,4,2,1} hold z-components
    const bool is_z = (cj == 1) || (cj == 2) || (cj == 4) || (cj == 8);
    const int zidx = is_z ? (__clz(cj) - 28) : 0;     // 8->0, 4->1, 2->2, 1->3

    float accS = 0.f, accQ = 0.f;

    // ============ per-warp pair loop (no block syncs) ============
    int it = 0;
    for (long pr = gwp; 2 * pr < B; pr += TWP, it++) {
        const int stage = it % DEPTH;
        const uint32_t mb = mymb0 + stage * 8;
        const long samp0 = 2 * pr;

        mbar_wait(mb, (it / DEPTH) & 1);

        // ---- pooling: conflict-free LDS.64 + packed f32x2 adds ----
        {
            const ull* p = (const ull*)(&buf[(wid * DEPTH + stage) * PAIR_FLOATS]) + f0;
#pragma unroll
            for (int smp = 0; smp < 2; smp++) {
                const int off = smp * 288;
                ull a0 = p[off + 0],  a1 = p[off + 1],  a2 = p[off + 2];
                ull b0 = p[off + 12], b1 = p[off + 13], b2 = p[off + 14];
                ull c0 = p[off + 24], c1 = p[off + 25], c2 = p[off + 26];
                ull t0, t1, t2, acc;
                ADDX2(t0, a0, a1);
                ADDX2(t1, b0, b1);
                ADDX2(t2, c0, c1);
                ADDX2(t0, t0, a2);
                ADDX2(t1, t1, b2);
                ADDX2(t2, t2, c2);
                ADDX2(acc, t0, t1);
                ADDX2(acc, acc, t2);
                float s = x2_hsum(acc);
                s += __shfl_down_sync(0xffffffffu, s, 4);
                if (phh == 0)
                    pw[wid][smp * 16 + pwy * 4 + pwx] = s * (1.f / 36.f);
            }
        }
        __syncwarp();   // sync1: pooled visible to angle lanes

        // ---- refill this slot for pair + DEPTH*TWP (overlaps compute) ----
        if (lid == 0) {
            long sn = 2 * (pr + (long)DEPTH * TWP);
            if (sn < B) {
                uint32_t bytes = (uint32_t)min(2L, B - sn) * 2304u;
                mbar_expect_tx(mb, bytes);
                bulk_ld(mybuf0 + stage * PAIR_BYTES, x + sn * 576, bytes, mb);
            }
        }

        // ---- angles + sincos: lanes 0..7 (4 per sample) ----
        if (lid < 8) {
            const int smp = lid >> 2, i = lid & 3;
            const float* pp = &pw[wid][smp * 16];
            float a0 = encs[64 + i], a1 = 0.f;
#pragma unroll
            for (int kk = 0; kk < 8; kk++) {
                a0 = fmaf(encs[i * 16 + kk], pp[kk], a0);
                a1 = fmaf(encs[i * 16 + 8 + kk], pp[8 + kk], a1);
            }
            float sv, cv;
            __sincosf(0.5f * (a0 + a1), &sv, &cv);
            pw[wid][32 + smp * 8 + i] = cv;
            pw[wid][32 + smp * 8 + 4 + i] = sv;
        }
        __syncwarp();   // sync2: cos/sin visible to circuit lanes

        // ---- circuit (packed): lanes 0-15 sample A, 16-31 sample B ----
        float v;
        {
            const float* c = &pw[wid][32 + half * 8];
            float c0 = c[0], c1 = c[1], c2 = c[2], c3 = c[3];
            float s0 = c[4], s1 = c[5], s2 = c[6], s3 = c[7];
            float p01[4];
            p01[0] = c0 * c1; p01[1] = c0 * s1; p01[2] = s0 * c1; p01[3] = s0 * s1;
            ull q0, q1;
            PACKX2(q0, c2 * c3, c2 * s3);
            PACKX2(q1, s2 * c3, s2 * s3);
            ull arp = 0, aip = 0;
#pragma unroll
            for (int j = 0; j < 4; j++) {
                ull pj, v0, v1;
                PACKX2(pj, p01[j], p01[j]);
                MULX2(v0, pj, q0);
                MULX2(v1, pj, q1);
                FMAX2(arp, frp[2 * j],     v0, arp);
                FMAX2(aip, fip[2 * j],     v0, aip);
                FMAX2(arp, frp[2 * j + 1], v1, arp);
                FMAX2(aip, fip[2 * j + 1], v1, aip);
            }
            float ar = x2_hsum(arp);
            float ai = x2_hsum(aip);
            v = ar * ar + ai * ai;   // p_cj
        }
        // ---- 16-point WHT butterfly: lane m -> sum_j (-1)^popc(j&m) p_j ----
#pragma unroll
        for (int b = 0; b < 4; b++) {
            float o = __shfl_xor_sync(0xffffffffu, v, 1 << b);
            v = (cj & (1 << b)) ? (o - v) : (v + o);
        }
        // lanes with cj in {8,4,2,1} now hold z components
        if (is_z && samp0 + half < B) {
            g_zbuf[(samp0 + half) * 4 + zidx] = v;
            accS += v;
            accQ += v * v;
        }
    }

    // ---- merge B-half accumulators into A-half z-lanes (deterministic) ----
    accS += __shfl_down_sync(0xffffffffu, accS, 16);
    accQ += __shfl_down_sync(0xffffffffu, accQ, 16);
    if (is_z && half == 0) {
        wacc[wid][zidx]     = accS;
        wacc[wid][4 + zidx] = accQ;
    }
    __syncthreads();
    if (tid < 4) {
        float S = 0.f, Q = 0.f;
#pragma unroll
        for (int w = 0; w < WPB; w++) {
            S += wacc[w][tid];
            Q += wacc[w][4 + tid];
        }
        g_part[blockIdx.x * 8 + tid]     = S;
        g_part[blockIdx.x * 8 + 4 + tid] = Q;
    }
    __threadfence();
    __syncthreads();
    if (tid == 0) {
        unsigned arr = atomicAdd(&g_bar, 1u) + 1u;
        unsigned target = ((arr + GRID - 1u) / GRID) * GRID;  // this launch's release
        while (*((volatile unsigned*)&g_bar) < target) {}
        __threadfence();
    }
    __syncthreads();

    // ---- redundant-but-deterministic stats reduction (each block) ----
    {
        float* red = &buf[0];   // reuse smem
        const int w = tid & 7, rr = tid >> 3;
        if (tid < 256) {
            float S = 0.f;
            for (int i = rr; i < GRID; i += 32) S += g_part[i * 8 + w];
            red[tid] = S;
        }
        __syncthreads();
#pragma unroll
        for (int step = 128; step >= 8; step >>= 1) {
            if (tid < step) red[tid] += red[tid + step];
            __syncthreads();
        }
        if (tid < 4) {
            float mean = red[tid] / (float)B;
            float var  = red[4 + tid] / (float)B - mean * mean;
            float sc   = gamma[tid] * rsqrtf(var + BN_EPS);
            stat[tid]     = sc;
            stat[4 + tid] = beta[tid] - mean * sc;
        }
        __syncthreads();
    }

    // ---- normalize (z is L2-resident) ----
    const float n0 = stat[0], n1 = stat[1], n2 = stat[2], n3 = stat[3];
    const float h0 = stat[4], h1 = stat[5], h2 = stat[6], h3 = stat[7];
    for (int b = blockIdx.x * NT + tid; b < B; b += GRID * NT) {
        float4 z = ((const float4*)g_zbuf)[b];
        ((float4*)out)[b] = make_float4(fmaf(z.x, n0, h0), fmaf(z.y, n1, h1),
                                        fmaf(z.z, n2, h2), fmaf(z.w, n3, h3));
    }
}

extern "C" void kernel_launch(void* const* d_in, const int* in_sizes, int n_in,
                              void* d_out, int out_size)
{
    const float* x      = (const float*)d_in[0];
    const float* enc_w  = (const float*)d_in[1];
    const float* enc_b  = (const float*)d_in[2];
    const float* vp     = (const float*)d_in[3];
    const float* gamma  = (const float*)d_in[4];
    const float* beta   = (const float*)d_in[5];

    const int B = in_sizes[0] / 576;   // [B,1,24,24]

    k_fused<<<GRID, NT>>>(x, enc_w, enc_b, vp, gamma, beta, (float*)d_out, B);
}

// round 15
// speedup vs baseline: 1.0800x; 1.0009x over previous
#include <cuda_runtime.h>
#include <math.h>
#include <stdint.h>

#define BN_EPS 1e-5f
#define WPB 8                  /* warps per block */
#define NT 256
#define DEPTH 3                /* per-warp ring depth (pairs) */
#define BPSM 2
#define NSM 148
#define GRID (NSM * BPSM)      /* 296 blocks, guaranteed co-resident */
#define TWP (GRID * WPB)       /* 2368 pair stride */
#define MAXB 65536
#define PAIR_FLOATS 1152
#define PAIR_BYTES  4608

typedef unsigned long long ull;

// persistent scratch (no allocation allowed)
__device__ float g_zbuf[MAXB * 4];
__device__ float g_part[GRID * 8];
__device__ unsigned g_bar;     // monotone arrival counter (never reset)

__device__ __forceinline__ uint32_t smem_u32(const void* p) {
    uint32_t a;
    asm("{ .reg .u64 t; cvta.to.shared.u64 t, %1; cvt.u32.u64 %0, t; }"
        : "=r"(a) : "l"(p));
    return a;
}
__device__ __forceinline__ void mbar_init(uint32_t m, uint32_t cnt) {
    asm volatile("mbarrier.init.shared.b64 [%0], %1;" :: "r"(m), "r"(cnt) : "memory");
}
__device__ __forceinline__ void mbar_expect_tx(uint32_t m, uint32_t bytes) {
    asm volatile("mbarrier.arrive.expect_tx.shared.b64 _, [%0], %1;"
                 :: "r"(m), "r"(bytes) : "memory");
}
__device__ __forceinline__ void bulk_ld(uint32_t dst, const void* src,
                                        uint32_t bytes, uint32_t m) {
    asm volatile("cp.async.bulk.shared::cluster.global.mbarrier::complete_tx::bytes "
                 "[%0], [%1], %2, [%3];"
                 :: "r"(dst), "l"(src), "r"(bytes), "r"(m) : "memory");
}
__device__ __forceinline__ void mbar_wait(uint32_t m, uint32_t phase) {
    uint32_t done;
    asm volatile("{\n\t.reg .pred p;\n\t"
                 "mbarrier.try_wait.parity.acquire.cta.shared::cta.b64 p, [%1], %2;\n\t"
                 "selp.b32 %0, 1, 0, p;\n\t}"
                 : "=r"(done) : "r"(m), "r"(phase) : "memory");
    if (!done) {
        asm volatile("{\n\t.reg .pred P1;\n\t"
                     "W_%=:\n\t"
                     "mbarrier.try_wait.parity.acquire.cta.shared::cta.b64 P1, [%0], %1, 0x989680;\n\t"
                     "@P1 bra.uni D_%=;\n\t"
                     "bra.uni W_%=;\n\t"
                     "D_%=:\n\t}" :: "r"(m), "r"(phase) : "memory");
    }
}

#define ADDX2(d, a, b) \
    asm("add.rn.f32x2 %0, %1, %2;" : "=l"(d) : "l"(a), "l"(b))
#define MULX2(d, a, b) \
    asm("mul.rn.f32x2 %0, %1, %2;" : "=l"(d) : "l"(a), "l"(b))
#define FMAX2(d, a, b, c) \
    asm("fma.rn.f32x2 %0, %1, %2, %3;" : "=l"(d) : "l"(a), "l"(b), "l"(c))
#define PACKX2(d, lo, hi) \
    asm("mov.b64 %0, {%1, %2};" : "=l"(d) : "r"(__float_as_uint(lo)), "r"(__float_as_uint(hi)))
__device__ __forceinline__ float x2_hsum(ull v) {
    uint32_t lo, hi;
    asm("mov.b64 {%0, %1}, %2;" : "=r"(lo), "=r"(hi) : "l"(v));
    return __uint_as_float(lo) + __uint_as_float(hi);
}

__global__ void __launch_bounds__(NT, BPSM) k_fused(
        const float* __restrict__ x,
        const float* __restrict__ enc_w,
        const float* __restrict__ enc_b,
        const float* __restrict__ vp,
        const float* __restrict__ gamma,
        const float* __restrict__ beta,
        float* __restrict__ out,
        int B)
{
    // per-warp private 3-deep pair rings: 8*3*1152 floats = 110592 B
    __shared__ __align__(128) float buf[WPB * DEPTH * PAIR_FLOATS];
    __shared__ __align__(8) uint64_t mbar[WPB * DEPTH];
    // overlay: Us (init-only, 512 floats) shares with pw(WPB*48)+wacc(WPB*8)
    __shared__ __align__(16) float ovl[512];
    __shared__ float encs[68];        // enc_w(64) + enc_b(4)
    __shared__ float stat[8];

    float* const Us = ovl;                         // [2*256] init only
    float (*const pw)[48] = (float(*)[48])ovl;     // [WPB][48] loop time
    float* const wacc = ovl + WPB * 48;            // [WPB*8] epilogue

    const int tid = threadIdx.x;
    const int wid = tid >> 5;
    const int lid = tid & 31;
    const long gwp = (long)blockIdx.x * WPB + wid;   // global pair id

    const uint32_t mybuf0 = smem_u32(&buf[wid * DEPTH * PAIR_FLOATS]);
    const uint32_t mymb0  = smem_u32(&mbar[wid * DEPTH]);

    // ---- stage encoder ----
    if (tid >= 32 && tid < 96)  encs[tid - 32] = enc_w[tid - 32];
    if (tid >= 96 && tid < 100) encs[64 + tid - 96] = enc_b[tid - 96];

    // ---- per-warp prologue: own mbarriers + DEPTH pair prefetches ----
    if (lid == 0) {
#pragma unroll
        for (int d = 0; d < DEPTH; d++) mbar_init(mymb0 + d * 8, 1);
        asm volatile("fence.proxy.async.shared::cta;" ::: "memory");
#pragma unroll
        for (int d = 0; d < DEPTH; d++) {
            long s0 = 2 * (gwp + (long)d * TWP);
            if (s0 < B) {
                uint32_t bytes = (uint32_t)min(2L, B - s0) * 2304u;
                mbar_expect_tx(mymb0 + d * 8, bytes);
                bulk_ld(mybuf0 + d * PAIR_BYTES, x + s0 * 576, bytes, mymb0 + d * 8);
            }
        }
    }

    // ---- warp 0: build fixed variational unitary U (fast sincos) ----
    if (tid < 16) {
        float re[16], im[16];
#pragma unroll
        for (int b = 0; b < 16; b++) { re[b] = (b == tid) ? 1.f : 0.f; im[b] = 0.f; }
#pragma unroll
        for (int d = 0; d < 2; d++) {
#pragma unroll
            for (int w = 0; w < 4; w++) {
                const int mask = 8 >> w;
                float cx, sx, cy, sy, cz, sz;
                __sincosf(0.5f * vp[d * 12 + w * 3 + 0], &sx, &cx);
                __sincosf(0.5f * vp[d * 12 + w * 3 + 1], &sy, &cy);
                __sincosf(0.5f * vp[d * 12 + w * 3 + 2], &sz, &cz);
#pragma unroll
                for (int b = 0; b < 16; b++) {
                    if (b & mask) continue;
                    const int b1 = b | mask;
                    float r0, i0, r1, i1;
                    r0 = re[b]; i0 = im[b]; r1 = re[b1]; i1 = im[b1];
                    re[b]  = cx * r0 + sx * i1;  im[b]  = cx * i0 - sx * r1;
                    re[b1] = cx * r1 + sx * i0;  im[b1] = cx * i1 - sx * r0;
                    r0 = re[b]; i0 = im[b]; r1 = re[b1]; i1 = im[b1];
                    re[b]  = cy * r0 - sy * r1;  im[b]  = cy * i0 - sy * i1;
                    re[b1] = sy * r0 + cy * r1;  im[b1] = sy * i0 + cy * i1;
                    r0 = re[b]; i0 = im[b]; r1 = re[b1]; i1 = im[b1];
                    re[b]  = cz * r0 + sz * i0;  im[b]  = cz * i0 - sz * r0;
                    re[b1] = cz * r1 - sz * i1;  im[b1] = cz * i1 + sz * r1;
                }
            }
#pragma unroll
            for (int c = 0; c < 4; c++) {
                const int tg = (c + 1) & 3;
                const int mc = 8 >> c, mt = 8 >> tg;
#pragma unroll
                for (int b = 0; b < 16; b++) {
                    if ((b & mc) && !(b & mt)) {
                        const int b1 = b | mt;
                        float tr = re[b], ti = im[b];
                        re[b] = re[b1]; im[b] = im[b1];
                        re[b1] = tr;    im[b1] = ti;
                    }
                }
            }
        }
#pragma unroll
        for (int b = 0; b < 16; b++) {
            Us[b * 16 + tid]       = re[b];
            Us[256 + b * 16 + tid] = im[b];
        }
    }
    __syncthreads();

    // ---- my U row: sign-folded by (-i)^popc(col), packed as f32x2 pairs ----
    const int cj = lid & 15;
    ull frp[8], fip[8];
#pragma unroll
    for (int i = 0; i < 8; i++) {
        float fr2[2], fi2[2];
#pragma unroll
        for (int h = 0; h < 2; h++) {
            const int t = 2 * i + h;
            float urv = Us[cj * 16 + t], uiv = Us[256 + cj * 16 + t];
            const int k4 = __popc(t) & 3;
            if (k4 == 0)      { fr2[h] = urv;  fi2[h] = uiv;  }
            else if (k4 == 1) { fr2[h] = uiv;  fi2[h] = -urv; }
            else if (k4 == 2) { fr2[h] = -urv; fi2[h] = -uiv; }
            else              { fr2[h] = -uiv; fi2[h] = urv;  }
        }
        PACKX2(frp[i], fr2[0], fr2[1]);
        PACKX2(fip[i], fi2[0], fi2[1]);
    }
    __syncthreads();   // ALL warps done reading Us before pw overwrites it

    // ---- conflict-free pooling lane decomposition ----
    const int pwy = lid >> 3;
    const int phh = (lid >> 2) & 1;
    const int pwx = lid & 3;
    const int f0  = 72 * pwy + 36 * phh + 3 * pwx;   // float2 units
    const int half = lid >> 4;                        // circuit: 0=A, 1=B

    // WHT output lanes: cj in {8,4,2,1} hold z-components
    const bool is_z = (cj == 1) || (cj == 2) || (cj == 4) || (cj == 8);
    const int zidx = is_z ? (__clz(cj) - 28) : 0;     // 8->0, 4->1, 2->2, 1->3

    float accS = 0.f, accQ = 0.f;

    // ============ per-warp pair loop (no block syncs) ============
    int it = 0;
    for (long pr = gwp; 2 * pr < B; pr += TWP, it++) {
        const int stage = it % DEPTH;
        const uint32_t mb = mymb0 + stage * 8;
        const long samp0 = 2 * pr;

        mbar_wait(mb, (it / DEPTH) & 1);

        // ---- pooling: conflict-free LDS.64 + packed f32x2 adds ----
        {
            const ull* p = (const ull*)(&buf[(wid * DEPTH + stage) * PAIR_FLOATS]) + f0;
#pragma unroll
            for (int smp = 0; smp < 2; smp++) {
                const int off = smp * 288;
                ull a0 = p[off + 0],  a1 = p[off + 1],  a2 = p[off + 2];
                ull b0 = p[off + 12], b1 = p[off + 13], b2 = p[off + 14];
                ull c0 = p[off + 24], c1 = p[off + 25], c2 = p[off + 26];
                ull t0, t1, t2, acc;
                ADDX2(t0, a0, a1);
                ADDX2(t1, b0, b1);
                ADDX2(t2, c0, c1);
                ADDX2(t0, t0, a2);
                ADDX2(t1, t1, b2);
                ADDX2(t2, t2, c2);
                ADDX2(acc, t0, t1);
                ADDX2(acc, acc, t2);
                float s = x2_hsum(acc);
                s += __shfl_down_sync(0xffffffffu, s, 4);
                if (phh == 0)
                    pw[wid][smp * 16 + pwy * 4 + pwx] = s * (1.f / 36.f);
            }
        }
        __syncwarp();   // sync1: pooled visible to angle lanes

        // ---- refill this slot for pair + DEPTH*TWP (overlaps compute) ----
        if (lid == 0) {
            long sn = 2 * (pr + (long)DEPTH * TWP);
            if (sn < B) {
                uint32_t bytes = (uint32_t)min(2L, B - sn) * 2304u;
                mbar_expect_tx(mb, bytes);
                bulk_ld(mybuf0 + stage * PAIR_BYTES, x + sn * 576, bytes, mb);
            }
        }

        // ---- angles + sincos: lanes 0..7 (4 per sample) ----
        if (lid < 8) {
            const int smp = lid >> 2, i = lid & 3;
            const float* pp = &pw[wid][smp * 16];
            float a0 = encs[64 + i], a1 = 0.f;
#pragma unroll
            for (int kk = 0; kk < 8; kk++) {
                a0 = fmaf(encs[i * 16 + kk], pp[kk], a0);
                a1 = fmaf(encs[i * 16 + 8 + kk], pp[8 + kk], a1);
            }
            float sv, cv;
            __sincosf(0.5f * (a0 + a1), &sv, &cv);
            pw[wid][32 + smp * 8 + i] = cv;
            pw[wid][32 + smp * 8 + 4 + i] = sv;
        }
        __syncwarp();   // sync2: cos/sin visible to circuit lanes

        // ---- circuit (packed): lanes 0-15 sample A, 16-31 sample B ----
        float v;
        {
            const float* c = &pw[wid][32 + half * 8];
            float c0 = c[0], c1 = c[1], c2 = c[2], c3 = c[3];
            float s0 = c[4], s1 = c[5], s2 = c[6], s3 = c[7];
            float p01[4];
            p01[0] = c0 * c1; p01[1] = c0 * s1; p01[2] = s0 * c1; p01[3] = s0 * s1;
            ull q0, q1;
            PACKX2(q0, c2 * c3, c2 * s3);
            PACKX2(q1, s2 * c3, s2 * s3);
            ull arp = 0, aip = 0;
#pragma unroll
            for (int j = 0; j < 4; j++) {
                ull pj, v0, v1;
                PACKX2(pj, p01[j], p01[j]);
                MULX2(v0, pj, q0);
                MULX2(v1, pj, q1);
                FMAX2(arp, frp[2 * j],     v0, arp);
                FMAX2(aip, fip[2 * j],     v0, aip);
                FMAX2(arp, frp[2 * j + 1], v1, arp);
                FMAX2(aip, fip[2 * j + 1], v1, aip);
            }
            float ar = x2_hsum(arp);
            float ai = x2_hsum(aip);
            v = ar * ar + ai * ai;   // p_cj
        }
        // ---- 16-point WHT butterfly: lane m -> sum_j (-1)^popc(j&m) p_j ----
#pragma unroll
        for (int b = 0; b < 4; b++) {
            float o = __shfl_xor_sync(0xffffffffu, v, 1 << b);
            v = (cj & (1 << b)) ? (o - v) : (v + o);
        }
        // lanes with cj in {8,4,2,1} now hold z components
        if (is_z && samp0 + half < B) {
            g_zbuf[(samp0 + half) * 4 + zidx] = v;
            accS += v;
            accQ += v * v;
        }
    }

    // ---- merge B-half accumulators into A-half z-lanes (deterministic) ----
    accS += __shfl_down_sync(0xffffffffu, accS, 16);
    accQ += __shfl_down_sync(0xffffffffu, accQ, 16);
    __syncthreads();   // all warps done with pw before wacc overlay use
    if (is_z && half == 0) {
        wacc[wid * 8 + zidx]     = accS;
        wacc[wid * 8 + 4 + zidx] = accQ;
    }
    __syncthreads();
    if (tid < 4) {
        float S = 0.f, Q = 0.f;
#pragma unroll
        for (int w = 0; w < WPB; w++) {
            S += wacc[w * 8 + tid];
            Q += wacc[w * 8 + 4 + tid];
        }
        g_part[blockIdx.x * 8 + tid]     = S;
        g_part[blockIdx.x * 8 + 4 + tid] = Q;
    }
    __threadfence();
    __syncthreads();
    if (tid == 0) {
        unsigned arr = atomicAdd(&g_bar, 1u) + 1u;
        unsigned target = ((arr + GRID - 1u) / GRID) * GRID;  // this launch's release
        while (*((volatile unsigned*)&g_bar) < target) {}
        __threadfence();
    }
    __syncthreads();

    // ---- redundant-but-deterministic stats reduction (each block) ----
    {
        float* red = &buf[0];   // reuse smem
        const int w = tid & 7, rr = tid >> 3;
        float S = 0.f;
        for (int i = rr; i < GRID; i += 32) S += g_part[i * 8 + w];
        red[tid] = S;
        __syncthreads();
#pragma unroll
        for (int step = 128; step >= 8; step >>= 1) {
            if (tid < step) red[tid] += red[tid + step];
            __syncthreads();
        }
        if (tid < 4) {
            float mean = red[tid] / (float)B;
            float var  = red[4 + tid] / (float)B - mean * mean;
            float sc   = gamma[tid] * rsqrtf(var + BN_EPS);
            stat[tid]     = sc;
            stat[4 + tid] = beta[tid] - mean * sc;
        }
        __syncthreads();
    }

    // ---- normalize (z is L2-resident) ----
    const float n0 = stat[0], n1 = stat[1], n2 = stat[2], n3 = stat[3];
    const float h0 = stat[4], h1 = stat[5], h2 = stat[6], h3 = stat[7];
    for (int b = blockIdx.x * NT + tid; b < B; b += GRID * NT) {
        float4 z = ((const float4*)g_zbuf)[b];
        ((float4*)out)[b] = make_float4(fmaf(z.x, n0, h0), fmaf(z.y, n1, h1),
                                        fmaf(z.z, n2, h2), fmaf(z.w, n3, h3));
    }
}

extern "C" void kernel_launch(void* const* d_in, const int* in_sizes, int n_in,
                              void* d_out, int out_size)
{
    const float* x      = (const float*)d_in[0];
    const float* enc_w  = (const float*)d_in[1];
    const float* enc_b  = (const float*)d_in[2];
    const float* vp     = (const float*)d_in[3];
    const float* gamma  = (const float*)d_in[4];
    const float* beta   = (const float*)d_in[5];

    const int B = in_sizes[0] / 576;   // [B,1,24,24]

    k_fused<<<GRID, NT>>>(x, enc_w, enc_b, vp, gamma, beta, (float*)d_out, B);
}